// round 1
// baseline (speedup 1.0000x reference)
#include <cuda_runtime.h>
#include <cuda_bf16.h>
#include <math.h>

// Problem constants (fixed by the reference)
#define B_SZ 2
#define SEQ 2048
#define DMODEL 1536
#define NHEADS 24
#define KVHEADS 6
#define HDIM 64
#define ROT 32
#define ROWS (B_SZ * SEQ)          // 4096
#define KVDIM (KVHEADS * HDIM)     // 384

// Scratch buffers (no allocation allowed -> device globals)
__device__ float g_Q[ROWS * DMODEL];
__device__ float g_K[ROWS * KVDIM];
__device__ float g_V[ROWS * KVDIM];
__device__ float g_A[ROWS * DMODEL];

// ---------------------------------------------------------------------------
// Generic tiled GEMM: C[M,N] = A[M,K] @ B[K,N]   (row-major everywhere)
// Tile: 64x64x16, 256 threads, 4x4 register micro-tile per thread.
// EPILOGUE: C = A@B + bias[n] + residual[m*N+n]
// ---------------------------------------------------------------------------
template<bool EPILOGUE>
__global__ __launch_bounds__(256)
void gemm64(const float* __restrict__ A, const float* __restrict__ Bm,
            float* __restrict__ C, int M, int N, int K,
            const float* __restrict__ bias, const float* __restrict__ residual)
{
    __shared__ float As[16][64];
    __shared__ float Bs[16][64];

    const int t  = threadIdx.x;
    const int tx = t & 15;          // 0..15
    const int ty = t >> 4;          // 0..15
    const int m0 = blockIdx.y * 64;
    const int n0 = blockIdx.x * 64;

    float acc[4][4];
#pragma unroll
    for (int i = 0; i < 4; ++i)
#pragma unroll
        for (int j = 0; j < 4; ++j) acc[i][j] = 0.f;

    const int ar = t >> 2;           // 0..63  A row within tile
    const int ac = (t & 3) << 2;     // 0,4,8,12
    const int br = t >> 4;           // 0..15  B row within tile
    const int bc = (t & 15) << 2;    // 0..60

    for (int k0 = 0; k0 < K; k0 += 16) {
        float4 a4 = *(const float4*)(A + (size_t)(m0 + ar) * K + k0 + ac);
        As[ac + 0][ar] = a4.x;
        As[ac + 1][ar] = a4.y;
        As[ac + 2][ar] = a4.z;
        As[ac + 3][ar] = a4.w;
        *(float4*)&Bs[br][bc] = *(const float4*)(Bm + (size_t)(k0 + br) * N + n0 + bc);
        __syncthreads();

#pragma unroll
        for (int kk = 0; kk < 16; ++kk) {
            float4 av = *(const float4*)&As[kk][ty << 2];
            float4 bv = *(const float4*)&Bs[kk][tx << 2];
            float a[4] = {av.x, av.y, av.z, av.w};
            float b[4] = {bv.x, bv.y, bv.z, bv.w};
#pragma unroll
            for (int i = 0; i < 4; ++i)
#pragma unroll
                for (int j = 0; j < 4; ++j)
                    acc[i][j] += a[i] * b[j];
        }
        __syncthreads();
    }

#pragma unroll
    for (int i = 0; i < 4; ++i) {
        int m = m0 + (ty << 2) + i;
        size_t rowoff = (size_t)m * N + n0 + (tx << 2);
#pragma unroll
        for (int j = 0; j < 4; ++j) {
            float v = acc[i][j];
            if (EPILOGUE) {
                int n = n0 + (tx << 2) + j;
                v += bias[n] + residual[rowoff + j];
            }
            C[rowoff + j] = v;
        }
    }
}

// ---------------------------------------------------------------------------
// Partial RoPE in place. X: [ROWS, nheads*64].  cos/sin: [SEQ, 32] with
// cos[:, d] == cos[:, d+16].  Each thread handles one (row, head, d<16) pair.
// ---------------------------------------------------------------------------
__global__ void rope_kernel(float* __restrict__ X,
                            const float* __restrict__ cosb,
                            const float* __restrict__ sinb,
                            int nheads, int total)
{
    int idx = blockIdx.x * blockDim.x + threadIdx.x;
    if (idx >= total) return;
    int d   = idx & 15;
    int tmp = idx >> 4;
    int h   = tmp % nheads;
    int row = tmp / nheads;
    int s   = row & (SEQ - 1);

    float c  = cosb[s * ROT + d];
    float sn = sinb[s * ROT + d];
    float* p = X + (size_t)row * (nheads * HDIM) + h * HDIM;
    float xr = p[d];
    float xi = p[d + 16];
    p[d]      = xr * c - xi * sn;
    p[d + 16] = xi * c + xr * sn;
}

// ---------------------------------------------------------------------------
// Flash-style attention.  grid = (SEQ/128, B*NHEADS), 128 threads.
// Each thread owns one q row (64 regs) and its fp32 accumulator (64 regs).
// KV processed in 64-row chunks staged in dynamic smem; chunk scores go
// through padded smem so exp() uses a stable per-row chunk max.
// ---------------------------------------------------------------------------
__global__ __launch_bounds__(128)
void attn_kernel(const float* __restrict__ Q, const float* __restrict__ K,
                 const float* __restrict__ V, float* __restrict__ O)
{
    extern __shared__ float sm[];
    float* Ks = sm;            // 64*64
    float* Vs = sm + 4096;     // 64*64
    float* Ss = sm + 8192;     // 128*65 (padded: stride 65 -> conflict-free)

    const int tid = threadIdx.x;
    const int bh  = blockIdx.y;
    const int b   = bh / NHEADS;
    const int h   = bh % NHEADS;
    const int kvh = h / (NHEADS / KVHEADS);   // h/4

    const int qrow = b * SEQ + blockIdx.x * 128 + tid;
    const float* qp = Q + (size_t)qrow * DMODEL + h * HDIM;

    float q[64];
#pragma unroll
    for (int d4 = 0; d4 < 16; ++d4) {
        float4 v = *(const float4*)(qp + d4 * 4);
        q[d4 * 4 + 0] = v.x; q[d4 * 4 + 1] = v.y;
        q[d4 * 4 + 2] = v.z; q[d4 * 4 + 3] = v.w;
    }

    float acc[64];
#pragma unroll
    for (int d = 0; d < 64; ++d) acc[d] = 0.f;
    float m = -1e30f;
    float l = 0.f;

    const size_t kvbase = (size_t)b * SEQ * KVDIM + kvh * HDIM;

    for (int j0 = 0; j0 < SEQ; j0 += 64) {
        // cooperative load of K,V chunk: 64 rows x 64 cols each
        for (int i = tid; i < 64 * 16; i += 128) {
            int r  = i >> 4;
            int c4 = (i & 15) << 2;
            size_t goff = kvbase + (size_t)(j0 + r) * KVDIM + c4;
            *(float4*)&Ks[r * 64 + c4] = *(const float4*)(K + goff);
            *(float4*)&Vs[r * 64 + c4] = *(const float4*)(V + goff);
        }
        __syncthreads();

        // pass A: scores for this chunk + chunk max
        float cmax = -1e30f;
        float* srow = Ss + tid * 65;
        for (int j = 0; j < 64; ++j) {
            const float4* kr = (const float4*)(Ks + j * 64);
            float s = 0.f;
#pragma unroll
            for (int d4 = 0; d4 < 16; ++d4) {
                float4 kv = kr[d4];
                s += q[d4 * 4 + 0] * kv.x + q[d4 * 4 + 1] * kv.y
                   + q[d4 * 4 + 2] * kv.z + q[d4 * 4 + 3] * kv.w;
            }
            s *= 0.125f;                      // 1/sqrt(64)
            cmax = fmaxf(cmax, s);
            srow[j] = s;
        }

        // online-softmax rescale
        float mnew = fmaxf(m, cmax);
        float corr = __expf(m - mnew);
        l *= corr;
#pragma unroll
        for (int d = 0; d < 64; ++d) acc[d] *= corr;

        // pass B: accumulate p * V
        for (int j = 0; j < 64; ++j) {
            float p = __expf(srow[j] - mnew);
            l += p;
            const float4* vr = (const float4*)(Vs + j * 64);
#pragma unroll
            for (int d4 = 0; d4 < 16; ++d4) {
                float4 vv = vr[d4];
                acc[d4 * 4 + 0] += p * vv.x;
                acc[d4 * 4 + 1] += p * vv.y;
                acc[d4 * 4 + 2] += p * vv.z;
                acc[d4 * 4 + 3] += p * vv.w;
            }
        }
        m = mnew;
        __syncthreads();
    }

    float inv_l = 1.f / l;
    float* op = O + (size_t)qrow * DMODEL + h * HDIM;
#pragma unroll
    for (int d4 = 0; d4 < 16; ++d4) {
        float4 v;
        v.x = acc[d4 * 4 + 0] * inv_l;
        v.y = acc[d4 * 4 + 1] * inv_l;
        v.z = acc[d4 * 4 + 2] * inv_l;
        v.w = acc[d4 * 4 + 3] * inv_l;
        *(float4*)(op + d4 * 4) = v;
    }
}

// ---------------------------------------------------------------------------
extern "C" void kernel_launch(void* const* d_in, const int* in_sizes, int n_in,
                              void* d_out, int out_size)
{
    const float* hidden = (const float*)d_in[0];
    const float* cosb   = (const float*)d_in[1];
    const float* sinb   = (const float*)d_in[2];
    const float* Wq     = (const float*)d_in[3];
    const float* Wk     = (const float*)d_in[4];
    const float* Wv     = (const float*)d_in[5];
    const float* Wo     = (const float*)d_in[6];
    const float* bo     = (const float*)d_in[7];
    float* out          = (float*)d_out;

    float *Qp, *Kp, *Vp, *Ap;
    cudaGetSymbolAddress((void**)&Qp, g_Q);
    cudaGetSymbolAddress((void**)&Kp, g_K);
    cudaGetSymbolAddress((void**)&Vp, g_V);
    cudaGetSymbolAddress((void**)&Ap, g_A);

    // QKV projections
    gemm64<false><<<dim3(DMODEL / 64, ROWS / 64), 256>>>(hidden, Wq, Qp,
        ROWS, DMODEL, DMODEL, nullptr, nullptr);
    gemm64<false><<<dim3(KVDIM / 64, ROWS / 64), 256>>>(hidden, Wk, Kp,
        ROWS, KVDIM, DMODEL, nullptr, nullptr);
    gemm64<false><<<dim3(KVDIM / 64, ROWS / 64), 256>>>(hidden, Wv, Vp,
        ROWS, KVDIM, DMODEL, nullptr, nullptr);

    // RoPE (partial, rot=32) on Q and K
    {
        int totq = ROWS * NHEADS * 16;
        rope_kernel<<<(totq + 255) / 256, 256>>>(Qp, cosb, sinb, NHEADS, totq);
        int totk = ROWS * KVHEADS * 16;
        rope_kernel<<<(totk + 255) / 256, 256>>>(Kp, cosb, sinb, KVHEADS, totk);
    }

    // Attention
    {
        const int smem = (4096 + 4096 + 128 * 65) * sizeof(float);  // 66048 B
        cudaFuncSetAttribute(attn_kernel,
                             cudaFuncAttributeMaxDynamicSharedMemorySize, smem);
        attn_kernel<<<dim3(SEQ / 128, B_SZ * NHEADS), 128, smem>>>(Qp, Kp, Vp, Ap);
    }

    // Output projection + bias + residual
    gemm64<true><<<dim3(DMODEL / 64, ROWS / 64), 256>>>(Ap, Wo, out,
        ROWS, DMODEL, DMODEL, bo, hidden);
}